// round 16
// baseline (speedup 1.0000x reference)
#include <cuda_runtime.h>
#include <cuda_fp16.h>
#include <cuda_fp8.h>
#include <math.h>
#include <stdint.h>

#define NN 100000
#define EE 3200000
#define FMAX 176
#define SCAN_NB 98   // ceil(100000/1024)
#define WSTRIDE (176 * 176)

// ---------------- scratch (static device globals; no allocation) -------------
__device__ __align__(16) __half g_hh0[(size_t)NN * FMAX];  // fp16 activations h
__device__ __align__(16) unsigned char g_f8a[(size_t)NN * FMAX]; // fp8 buffer A
__device__ __align__(16) unsigned char g_f8b[(size_t)NN * FMAX]; // fp8 buffer B
__device__ __align__(16) __half g_w16[11 * WSTRIDE];       // fp16 weights, [N][K] per layer
__device__ float g_ns[NN];
__device__ float g_nd[NN];
__device__ int   g_deg_in[NN];
__device__ int   g_deg_out[NN];
__device__ int   g_rowptr[NN + 1];
__device__ int   g_cursor[NN];
__device__ __align__(8) int2 g_csr[EE];    // (src, coef as half2 bits)
__device__ int   g_bsums[128];
__device__ float g_mean[FMAX];

__device__ __forceinline__ const unsigned char* pick_c(int s) { return s ? g_f8b : g_f8a; }
__device__ __forceinline__ unsigned char* pick(int s) { return s ? g_f8b : g_f8a; }

// ---------------- fp8 helpers -------------------------------------------------
__device__ __forceinline__ unsigned f8x4_pack(float a, float b, float c, float d) {
    unsigned lo = __nv_cvt_float2_to_fp8x2(make_float2(a, b), __NV_SATFINITE, __NV_E4M3);
    unsigned hi = __nv_cvt_float2_to_fp8x2(make_float2(c, d), __NV_SATFINITE, __NV_E4M3);
    return (lo & 0xffff) | (hi << 16);
}

__device__ __forceinline__ void f8acc8(unsigned w0, unsigned w1, __half2 cf, __half2* hacc) {
    __half2_raw p0 = __nv_cvt_fp8x2_to_halfraw2((__nv_fp8x2_storage_t)(w0 & 0xffff), __NV_E4M3);
    __half2_raw p1 = __nv_cvt_fp8x2_to_halfraw2((__nv_fp8x2_storage_t)(w0 >> 16), __NV_E4M3);
    __half2_raw p2 = __nv_cvt_fp8x2_to_halfraw2((__nv_fp8x2_storage_t)(w1 & 0xffff), __NV_E4M3);
    __half2_raw p3 = __nv_cvt_fp8x2_to_halfraw2((__nv_fp8x2_storage_t)(w1 >> 16), __NV_E4M3);
    hacc[0] = __hfma2(*reinterpret_cast<__half2*>(&p0), cf, hacc[0]);
    hacc[1] = __hfma2(*reinterpret_cast<__half2*>(&p1), cf, hacc[1]);
    hacc[2] = __hfma2(*reinterpret_cast<__half2*>(&p2), cf, hacc[2]);
    hacc[3] = __hfma2(*reinterpret_cast<__half2*>(&p3), cf, hacc[3]);
}

__device__ __forceinline__ void f8acc16(uint4 v, __half2 cf, __half2* hacc) {
    f8acc8(v.x, v.y, cf, hacc);
    f8acc8(v.z, v.w, cf, hacc + 4);
}

// gather 16 cols starting at c over edge range [beg,end), 4-way unrolled
__device__ __forceinline__ void gather16(const unsigned char* __restrict__ fsrc, int F, int c,
                                         int beg, int end, __half2* hacc) {
    int e = beg;
    for (; e + 3 < end; e += 4) {
        int2 c0 = g_csr[e], c1 = g_csr[e + 1], c2 = g_csr[e + 2], c3 = g_csr[e + 3];
        uint4 v0 = *reinterpret_cast<const uint4*>(fsrc + (size_t)c0.x * F + c);
        uint4 v1 = *reinterpret_cast<const uint4*>(fsrc + (size_t)c1.x * F + c);
        uint4 v2 = *reinterpret_cast<const uint4*>(fsrc + (size_t)c2.x * F + c);
        uint4 v3 = *reinterpret_cast<const uint4*>(fsrc + (size_t)c3.x * F + c);
        f8acc16(v0, *reinterpret_cast<__half2*>(&c0.y), hacc);
        f8acc16(v1, *reinterpret_cast<__half2*>(&c1.y), hacc);
        f8acc16(v2, *reinterpret_cast<__half2*>(&c2.y), hacc);
        f8acc16(v3, *reinterpret_cast<__half2*>(&c3.y), hacc);
    }
    for (; e < end; e++) {
        int2 ce = g_csr[e];
        uint4 v = *reinterpret_cast<const uint4*>(fsrc + (size_t)ce.x * F + c);
        f8acc16(v, *reinterpret_cast<__half2*>(&ce.y), hacc);
    }
}

// ---------------- preprocessing ---------------------------------------------
__global__ void k_zero() {
    int i = blockIdx.x * blockDim.x + threadIdx.x;
    if (i < NN) { g_deg_in[i] = 0; g_deg_out[i] = 0; }
    if (i < FMAX) g_mean[i] = 0.f;
}

__global__ void k_deg(const int* __restrict__ src, const int* __restrict__ dst) {
    int e = blockIdx.x * blockDim.x + threadIdx.x;
    if (e < EE) {
        atomicAdd(&g_deg_out[src[e]], 1);
        atomicAdd(&g_deg_in[dst[e]], 1);
    }
}

__global__ void k_scan1() {
    __shared__ int s[1024];
    int i = blockIdx.x * 1024 + threadIdx.x;
    int v = (i < NN) ? g_deg_in[i] : 0;
    s[threadIdx.x] = v;
    __syncthreads();
    for (int off = 1; off < 1024; off <<= 1) {
        int t = 0;
        if (threadIdx.x >= off) t = s[threadIdx.x - off];
        __syncthreads();
        s[threadIdx.x] += t;
        __syncthreads();
    }
    if (i < NN) g_rowptr[i] = s[threadIdx.x] - v;  // exclusive
    if (threadIdx.x == 1023) g_bsums[blockIdx.x] = s[1023];
}

__global__ void k_scan2(int nb) {
    __shared__ int s[128];
    int t = threadIdx.x;
    int v = (t < nb) ? g_bsums[t] : 0;
    s[t] = v;
    __syncthreads();
    for (int off = 1; off < 128; off <<= 1) {
        int u = 0;
        if (t >= off) u = s[t - off];
        __syncthreads();
        s[t] += u;
        __syncthreads();
    }
    if (t < nb) g_bsums[t] = s[t] - v;   // exclusive
}

__global__ void k_scan3() {
    int i = blockIdx.x * blockDim.x + threadIdx.x;
    if (i < NN) {
        int r = g_rowptr[i] + g_bsums[i >> 10];
        g_rowptr[i] = r;
        g_cursor[i] = r;
        int o = g_deg_out[i];
        g_ns[i] = (o > 0) ? rsqrtf((float)o) : 0.f;
        int d = g_deg_in[i];
        g_nd[i] = (d > 0) ? rsqrtf((float)d) : 0.f;
    }
    if (i == 0) g_rowptr[NN] = EE;
}

__global__ void k_scatter(const int* __restrict__ src, const int* __restrict__ dst,
                          const float* __restrict__ edata,
                          const float* __restrict__ mu, const float* __restrict__ sigma) {
    int e = blockIdx.x * blockDim.x + threadIdx.x;
    if (e < EE) {
        int s = src[e];
        int d = dst[e];
        float ed = edata[e];
        float m = *mu, sg = *sigma;
        float w = (ed == 1.0f) ? 1.0f : expf(-((ed - m) * (ed - m)) / sg);
        float cf = g_ns[s] * w;
        __half2 h2 = __half2half2(__float2half(cf));
        int bits;
        *reinterpret_cast<__half2*>(&bits) = h2;
        int p = atomicAdd(&g_cursor[d], 1);
        g_csr[p] = make_int2(s, bits);
    }
}

__global__ void k_copyx(const float* __restrict__ x) {
    size_t i = (size_t)blockIdx.x * blockDim.x + threadIdx.x;
    size_t stride = (size_t)gridDim.x * blockDim.x;
    for (; i < (size_t)NN * 64; i += stride) {
        // initial fp16 copy is never read (layer 0 is fused and reads fp8)
        g_f8a[i] = (unsigned char)__nv_cvt_float_to_fp8(x[i], __NV_SATFINITE, __NV_E4M3);
    }
}

// ---------------- weight conversion: fp32 [K,N] -> fp16 [N,K] ----------------
struct WConv {
    const float* w[11];
    int K[11];
    int N[11];
};

__global__ void k_wconv(WConv p) {
    int layer = blockIdx.y;
    int K = p.K[layer], N = p.N[layer];
    int tot = K * N;
    const float* w = p.w[layer];
    __half* out = g_w16 + (size_t)layer * WSTRIDE;
    for (int i = blockIdx.x * blockDim.x + threadIdx.x; i < tot; i += gridDim.x * blockDim.x) {
        int k = i / N, n = i % N;
        out[n * K + k] = __float2half(w[i]);
    }
}

// ---------------- HMMA helper -------------------------------------------------
__device__ __forceinline__ void mma16816(float* d, const uint32_t* a, const uint32_t* b) {
    asm volatile(
        "mma.sync.aligned.m16n8k16.row.col.f32.f16.f16.f32 "
        "{%0,%1,%2,%3}, {%4,%5,%6,%7}, {%8,%9}, {%0,%1,%2,%3};\n"
        : "+f"(d[0]), "+f"(d[1]), "+f"(d[2]), "+f"(d[3])
        : "r"(a[0]), "r"(a[1]), "r"(a[2]), "r"(a[3]), "r"(b[0]), "r"(b[1]));
}

// ---------------- FUSED spmm+gemm layer (hybrid 512 threads) ------------------
// Block = 128 nodes. Phase A (all 512 threads): aggregate fp8 -> As smem (fp16).
// Phase B: warps 0-7 run the proven 32x32-warptile GEMM; warps 8-15 only help
// load Bs and participate in barriers.
template<int WH>
__global__ void __launch_bounds__(512)
k_fused(const float* __restrict__ bias, int layer, int K, int Nn,
        int lpn, int sel) {
    extern __shared__ __half sm[];
    int sak = K + 8;
    __half* As = sm;                   // 128 * sak
    __half* Bs = sm + 128 * sak;       // 64 * sak
    const unsigned char* fin = pick_c(sel);
    unsigned char* fout = pick(1 - sel);
    const __half* Wl = g_w16 + (size_t)layer * WSTRIDE;
    int tid = threadIdx.x;             // 512
    int bm = blockIdx.x * 128;

    // ---- phase A: aggregation into As (all threads) ----
    for (int item = tid; item < 128 * lpn; item += 512) {
        int nl = item / lpn;
        int node = bm + nl;
        if (node < NN) {
            int c = (item - nl * lpn) * 16;
            __half2 hacc[8];
            #pragma unroll
            for (int q = 0; q < 8; q++) hacc[q] = __half2half2(__ushort_as_half(0));
            gather16(fin, K, c, g_rowptr[node], g_rowptr[node + 1], hacc);
            __half2 nd2 = __half2half2(__float2half(g_nd[node]));
            #pragma unroll
            for (int q = 0; q < 8; q++) hacc[q] = __hmul2(hacc[q], nd2);
            int4* op = reinterpret_cast<int4*>(&As[nl * sak + c]);
            op[0] = *reinterpret_cast<int4*>(&hacc[0]);
            op[1] = *reinterpret_cast<int4*>(&hacc[4]);
        }
    }
    __syncthreads();

    // ---- phase B: GEMM, warps 0-7 compute (R12 tiling), all warps sync ----
    int lane = tid & 31, wid = tid >> 5;
    int warpM = wid >> 1, warpN = wid & 1;   // valid for wid < 8
    int g = lane >> 2, tg2 = (lane & 3) * 2;
    int kq8 = K >> 3;                  // int4 loads per B row

    for (int nc = 0; nc < Nn; nc += 64) {
        for (int idx = tid; idx < 64 * kq8; idx += 512) {
            int row = idx / kq8, q = idx - row * kq8;
            int gn = nc + row;
            int4 v = make_int4(0, 0, 0, 0);
            if (gn < Nn)
                v = *reinterpret_cast<const int4*>(Wl + (size_t)gn * K + q * 8);
            *reinterpret_cast<int4*>(&Bs[row * sak + q * 8]) = v;
        }
        __syncthreads();

        if (wid < 8) {
            float acc[2][4][4] = {};
            for (int kk = 0; kk < K; kk += 16) {
                uint32_t a[2][4], bf[4][2];
                #pragma unroll
                for (int mt = 0; mt < 2; mt++) {
                    int r = warpM * 32 + mt * 16 + g;
                    a[mt][0] = *reinterpret_cast<const uint32_t*>(&As[r * sak + kk + tg2]);
                    a[mt][1] = *reinterpret_cast<const uint32_t*>(&As[(r + 8) * sak + kk + tg2]);
                    a[mt][2] = *reinterpret_cast<const uint32_t*>(&As[r * sak + kk + tg2 + 8]);
                    a[mt][3] = *reinterpret_cast<const uint32_t*>(&As[(r + 8) * sak + kk + tg2 + 8]);
                }
                #pragma unroll
                for (int nt = 0; nt < 4; nt++) {
                    int n = warpN * 32 + nt * 8 + g;
                    bf[nt][0] = *reinterpret_cast<const uint32_t*>(&Bs[n * sak + kk + tg2]);
                    bf[nt][1] = *reinterpret_cast<const uint32_t*>(&Bs[n * sak + kk + tg2 + 8]);
                }
                #pragma unroll
                for (int mt = 0; mt < 2; mt++)
                    #pragma unroll
                    for (int nt = 0; nt < 4; nt++)
                        mma16816(acc[mt][nt], a[mt], bf[nt]);
            }

            // epilogue for this n-chunk
            #pragma unroll
            for (int mt = 0; mt < 2; mt++) {
                #pragma unroll
                for (int nt = 0; nt < 4; nt++) {
                    int r0 = bm + warpM * 32 + mt * 16 + g;
                    int c0 = nc + warpN * 32 + nt * 8 + tg2;
                    float* cc = acc[mt][nt];
                    #pragma unroll
                    for (int hf = 0; hf < 2; hf++) {
                        int r = r0 + hf * 8;
                        if (r < NN && c0 + 1 < Nn) {
                            float v0 = cc[hf * 2 + 0] + bias[c0];
                            float v1 = cc[hf * 2 + 1] + bias[c0 + 1];
                            v0 = (v0 > 0.f) ? v0 : 0.01f * v0;
                            v1 = (v1 > 0.f) ? v1 : 0.01f * v1;
                            if (WH) {
                                *reinterpret_cast<__half2*>(g_hh0 + (size_t)r * Nn + c0) =
                                    __floats2half2_rn(v0, v1);
                            }
                            *reinterpret_cast<unsigned short*>(fout + (size_t)r * Nn + c0) =
                                (unsigned short)__nv_cvt_float2_to_fp8x2(make_float2(v0, v1),
                                                                         __NV_SATFINITE, __NV_E4M3);
                        }
                    }
                }
            }
        }
        __syncthreads();
    }
}

// ---------------- standalone spmm (gemm-first layers; post-gemm) --------------
// reads z fp8 from f8[selz], writes h -> f8[1-selz] only
__global__ void k_spmm1(int F, int lpn, const float* __restrict__ bias, int selz) {
    int t = blockIdx.x * blockDim.x + threadIdx.x;
    int node = t / lpn;
    if (node >= NN) return;
    int c = (t - node * lpn) * 16;

    const unsigned char* fin = pick_c(selz);
    unsigned char* fout = pick(1 - selz);

    __half2 hacc[8];
    #pragma unroll
    for (int q = 0; q < 8; q++) hacc[q] = __half2half2(__ushort_as_half(0));
    gather16(fin, F, c, g_rowptr[node], g_rowptr[node + 1], hacc);

    float nd = g_nd[node];
    float acc[16];
    #pragma unroll
    for (int q = 0; q < 8; q++) {
        float2 f = __half22float2(hacc[q]);
        acc[2 * q + 0] = f.x * nd;
        acc[2 * q + 1] = f.y * nd;
    }
    #pragma unroll
    for (int j = 0; j < 16; j++) {
        float v = acc[j] + bias[c + j];
        acc[j] = (v > 0.f) ? v : 0.01f * v;
    }
    uint4 f8o;
    f8o.x = f8x4_pack(acc[0], acc[1], acc[2], acc[3]);
    f8o.y = f8x4_pack(acc[4], acc[5], acc[6], acc[7]);
    f8o.z = f8x4_pack(acc[8], acc[9], acc[10], acc[11]);
    f8o.w = f8x4_pack(acc[12], acc[13], acc[14], acc[15]);
    *reinterpret_cast<uint4*>(fout + (size_t)node * F + c) = f8o;
}

// ---------------- standalone gemm (gemm-first layers; pre-agg) ----------------
// z = g_hh0 @ W  -> f8[selout] (fp8 only)
#define SA 80
__global__ void k_gemm1(int layer, int K, int Nn, int selout) {
    const __half* A = g_hh0;
    unsigned char* fout = pick(selout);
    const __half* Wl = g_w16 + (size_t)layer * WSTRIDE;
    __shared__ __half As[128 * SA];
    __shared__ __half Bs[64 * SA];

    int tid = threadIdx.x;
    int lane = tid & 31, wid = tid >> 5;
    int warpM = wid >> 1, warpN = wid & 1;
    int g = lane >> 2, tg2 = (lane & 3) * 2;
    int bm = blockIdx.y * 128, bn = blockIdx.x * 64;

    float acc[2][4][4] = {};

    for (int kc = 0; kc < K; kc += 64) {
        #pragma unroll
        for (int t = 0; t < 4; t++) {
            int idx = tid + t * 256;
            int row = idx >> 3, q = idx & 7;
            int gm = bm + row, o = kc + q * 8;
            int4 v = make_int4(0, 0, 0, 0);
            if (gm < NN && o < K)
                v = *reinterpret_cast<const int4*>(A + (size_t)gm * K + o);
            *reinterpret_cast<int4*>(&As[row * SA + q * 8]) = v;
        }
        #pragma unroll
        for (int t = 0; t < 2; t++) {
            int idx = tid + t * 256;
            int row = idx >> 3, q = idx & 7;
            int gn = bn + row, o = kc + q * 8;
            int4 v = make_int4(0, 0, 0, 0);
            if (gn < Nn && o < K)
                v = *reinterpret_cast<const int4*>(Wl + (size_t)gn * K + o);
            *reinterpret_cast<int4*>(&Bs[row * SA + q * 8]) = v;
        }
        __syncthreads();

        #pragma unroll
        for (int ks = 0; ks < 4; ks++) {
            int kk = ks * 16;
            uint32_t a[2][4], bf[4][2];
            #pragma unroll
            for (int mt = 0; mt < 2; mt++) {
                int r = warpM * 32 + mt * 16 + g;
                a[mt][0] = *reinterpret_cast<const uint32_t*>(&As[r * SA + kk + tg2]);
                a[mt][1] = *reinterpret_cast<const uint32_t*>(&As[(r + 8) * SA + kk + tg2]);
                a[mt][2] = *reinterpret_cast<const uint32_t*>(&As[r * SA + kk + tg2 + 8]);
                a[mt][3] = *reinterpret_cast<const uint32_t*>(&As[(r + 8) * SA + kk + tg2 + 8]);
            }
            #pragma unroll
            for (int nt = 0; nt < 4; nt++) {
                int n = warpN * 32 + nt * 8 + g;
                bf[nt][0] = *reinterpret_cast<const uint32_t*>(&Bs[n * SA + kk + tg2]);
                bf[nt][1] = *reinterpret_cast<const uint32_t*>(&Bs[n * SA + kk + tg2 + 8]);
            }
            #pragma unroll
            for (int mt = 0; mt < 2; mt++)
                #pragma unroll
                for (int nt = 0; nt < 4; nt++)
                    mma16816(acc[mt][nt], a[mt], bf[nt]);
        }
        __syncthreads();
    }

    #pragma unroll
    for (int mt = 0; mt < 2; mt++) {
        #pragma unroll
        for (int nt = 0; nt < 4; nt++) {
            int r0 = bm + warpM * 32 + mt * 16 + g;
            int c0 = bn + warpN * 32 + nt * 8 + tg2;
            float* cc = acc[mt][nt];
            #pragma unroll
            for (int hf = 0; hf < 2; hf++) {
                int r = r0 + hf * 8;
                if (r < NN && c0 + 1 < Nn) {
                    *reinterpret_cast<unsigned short*>(fout + (size_t)r * Nn + c0) =
                        (unsigned short)__nv_cvt_float2_to_fp8x2(
                            make_float2(cc[hf * 2 + 0], cc[hf * 2 + 1]),
                            __NV_SATFINITE, __NV_E4M3);
                }
            }
        }
    }
}

// ---------------- pooling + head ---------------------------------------------
__global__ void k_mean(int F) {
    int j = threadIdx.x;      // blockDim = F (160)
    float acc = 0.f;
    for (int n = blockIdx.x; n < NN; n += gridDim.x)
        acc += __half2float(g_hh0[(size_t)n * F + j]);
    atomicAdd(&g_mean[j], acc);
}

__global__ void k_head(const float* __restrict__ Wd1, const float* __restrict__ bd1,
                       const float* __restrict__ Wd2, const float* __restrict__ bd2,
                       float* __restrict__ out) {
    __shared__ float hm[160];
    __shared__ float hd[140];
    int t = threadIdx.x;
    if (t < 160) {
        float v = g_mean[t] / (float)NN;
        hm[t] = (v > 0.f) ? v : 0.01f * v;
    }
    __syncthreads();
    if (t < 140) {
        float s = bd1[t];
        for (int k = 0; k < 160; k++) s += hm[k] * Wd1[k * 140 + t];
        hd[t] = (s > 0.f) ? s : 0.01f * s;
    }
    __syncthreads();
    if (t < 2) {
        float s = bd2[t];
        for (int k = 0; k < 140; k++) s += hd[k] * Wd2[k * 2 + t];
        out[t] = 1.0f / (1.0f + expf(-s));
    }
}

// ---------------- launch ------------------------------------------------------
extern "C" void kernel_launch(void* const* d_in, const int* in_sizes, int n_in,
                              void* d_out, int out_size) {
    const float* x     = (const float*)d_in[0];
    const int*   src   = (const int*)d_in[1];
    const int*   dst   = (const int*)d_in[2];
    const float* edata = (const float*)d_in[3];
    const float* W[11];
    const float* b[11];
    for (int i = 0; i < 11; i++) {
        W[i] = (const float*)d_in[4 + 2 * i];
        b[i] = (const float*)d_in[5 + 2 * i];
    }
    const float* Wd1 = (const float*)d_in[26];
    const float* bd1 = (const float*)d_in[27];
    const float* Wd2 = (const float*)d_in[28];
    const float* bd2 = (const float*)d_in[29];
    const float* mu    = (const float*)d_in[30];
    const float* sigma = (const float*)d_in[31];
    float* out = (float*)d_out;

    static const int dims[12] = {64, 80, 160, 112, 160, 176, 96, 144, 96, 128, 96, 160};
    static const int gfirst[11] = {0, 0, 1, 0, 0, 1, 0, 1, 0, 1, 0};

    cudaFuncSetAttribute(k_fused<0>, cudaFuncAttributeMaxDynamicSharedMemorySize, 73728);
    cudaFuncSetAttribute(k_fused<1>, cudaFuncAttributeMaxDynamicSharedMemorySize, 73728);

    k_zero<<<(NN + 255) / 256, 256>>>();
    k_deg<<<(EE + 255) / 256, 256>>>(src, dst);
    k_scan1<<<SCAN_NB, 1024>>>();
    k_scan2<<<1, 128>>>(SCAN_NB);
    k_scan3<<<(NN + 255) / 256, 256>>>();
    k_scatter<<<(EE + 255) / 256, 256>>>(src, dst, edata, mu, sigma);
    k_copyx<<<4096, 256>>>(x);

    WConv wc;
    for (int i = 0; i < 11; i++) {
        wc.w[i] = W[i];
        wc.K[i] = dims[i];
        wc.N[i] = dims[i + 1];
    }
    k_wconv<<<dim3(121, 11), 256>>>(wc);

    int cur = 0;   // which f8 buffer holds the current layer input (0=a, 1=b)
    for (int i = 0; i < 11; i++) {
        int Fi = dims[i], Fo = dims[i + 1];
        if (gfirst[i]) {
            dim3 grid((Fo + 63) / 64, (NN + 127) / 128);
            k_gemm1<<<grid, 256>>>(i, Fi, Fo, 1 - cur);
            int lpn = Fo >> 4;
            int blocks = (NN * lpn + 255) / 256;
            k_spmm1<<<blocks, 256>>>(Fo, lpn, b[i], 1 - cur);
            // cur unchanged
        } else {
            int lpn = Fi >> 4;
            int smem = (128 + 64) * (Fi + 8) * 2;
            int need_h = (i == 10) || gfirst[i + 1];
            if (need_h)
                k_fused<1><<<(NN + 127) / 128, 512, smem>>>(b[i], i, Fi, Fo, lpn, cur);
            else
                k_fused<0><<<(NN + 127) / 128, 512, smem>>>(b[i], i, Fi, Fo, lpn, cur);
            cur ^= 1;
        }
    }

    k_mean<<<512, 160>>>(160);
    k_head<<<1, 160>>>(Wd1, bd1, Wd2, bd2, out);
}

// round 17
// speedup vs baseline: 1.0763x; 1.0763x over previous
#include <cuda_runtime.h>
#include <cuda_fp16.h>
#include <cuda_fp8.h>
#include <math.h>
#include <stdint.h>

#define NN 100000
#define EE 3200000
#define FMAX 176
#define SCAN_NB 98   // ceil(100000/1024)
#define WSTRIDE (176 * 176)

// ---------------- scratch (static device globals; no allocation) -------------
__device__ __align__(16) __half g_hh0[(size_t)NN * FMAX];  // fp16 activations (final layer only)
__device__ __align__(16) unsigned char g_f8a[(size_t)NN * FMAX]; // fp8 buffer A
__device__ __align__(16) unsigned char g_f8b[(size_t)NN * FMAX]; // fp8 buffer B
__device__ __align__(16) __half g_w16[11 * WSTRIDE];       // fp16 weights, [N][K] per layer
__device__ float g_ns[NN];
__device__ float g_nd[NN];
__device__ int   g_deg_in[NN];
__device__ int   g_deg_out[NN];
__device__ int   g_rowptr[NN + 1];
__device__ int   g_cursor[NN];
__device__ __align__(8) int2 g_csr[EE];    // (src, coef as half2 bits)
__device__ int   g_bsums[128];
__device__ float g_mean[FMAX];

__device__ __forceinline__ const unsigned char* pick_c(int s) { return s ? g_f8b : g_f8a; }
__device__ __forceinline__ unsigned char* pick(int s) { return s ? g_f8b : g_f8a; }

// ---------------- fp8 helpers -------------------------------------------------
__device__ __forceinline__ unsigned f8x4_pack(float a, float b, float c, float d) {
    unsigned lo = __nv_cvt_float2_to_fp8x2(make_float2(a, b), __NV_SATFINITE, __NV_E4M3);
    unsigned hi = __nv_cvt_float2_to_fp8x2(make_float2(c, d), __NV_SATFINITE, __NV_E4M3);
    return (lo & 0xffff) | (hi << 16);
}

__device__ __forceinline__ void f8acc8(unsigned w0, unsigned w1, __half2 cf, __half2* hacc) {
    __half2_raw p0 = __nv_cvt_fp8x2_to_halfraw2((__nv_fp8x2_storage_t)(w0 & 0xffff), __NV_E4M3);
    __half2_raw p1 = __nv_cvt_fp8x2_to_halfraw2((__nv_fp8x2_storage_t)(w0 >> 16), __NV_E4M3);
    __half2_raw p2 = __nv_cvt_fp8x2_to_halfraw2((__nv_fp8x2_storage_t)(w1 & 0xffff), __NV_E4M3);
    __half2_raw p3 = __nv_cvt_fp8x2_to_halfraw2((__nv_fp8x2_storage_t)(w1 >> 16), __NV_E4M3);
    hacc[0] = __hfma2(*reinterpret_cast<__half2*>(&p0), cf, hacc[0]);
    hacc[1] = __hfma2(*reinterpret_cast<__half2*>(&p1), cf, hacc[1]);
    hacc[2] = __hfma2(*reinterpret_cast<__half2*>(&p2), cf, hacc[2]);
    hacc[3] = __hfma2(*reinterpret_cast<__half2*>(&p3), cf, hacc[3]);
}

__device__ __forceinline__ void f8acc16(uint4 v, __half2 cf, __half2* hacc) {
    f8acc8(v.x, v.y, cf, hacc);
    f8acc8(v.z, v.w, cf, hacc + 4);
}

// convert 8 fp8 (uint2) -> 4 half2 (int4 image), no scaling
__device__ __forceinline__ int4 f8x8_to_h8(uint2 v) {
    __half2_raw p0 = __nv_cvt_fp8x2_to_halfraw2((__nv_fp8x2_storage_t)(v.x & 0xffff), __NV_E4M3);
    __half2_raw p1 = __nv_cvt_fp8x2_to_halfraw2((__nv_fp8x2_storage_t)(v.x >> 16), __NV_E4M3);
    __half2_raw p2 = __nv_cvt_fp8x2_to_halfraw2((__nv_fp8x2_storage_t)(v.y & 0xffff), __NV_E4M3);
    __half2_raw p3 = __nv_cvt_fp8x2_to_halfraw2((__nv_fp8x2_storage_t)(v.y >> 16), __NV_E4M3);
    __half2 h[4];
    h[0] = *reinterpret_cast<__half2*>(&p0);
    h[1] = *reinterpret_cast<__half2*>(&p1);
    h[2] = *reinterpret_cast<__half2*>(&p2);
    h[3] = *reinterpret_cast<__half2*>(&p3);
    return *reinterpret_cast<int4*>(h);
}

// gather 16 cols starting at c over edge range [beg,end), 4-way unrolled
__device__ __forceinline__ void gather16(const unsigned char* __restrict__ fsrc, int F, int c,
                                         int beg, int end, __half2* hacc) {
    int e = beg;
    for (; e + 3 < end; e += 4) {
        int2 c0 = g_csr[e], c1 = g_csr[e + 1], c2 = g_csr[e + 2], c3 = g_csr[e + 3];
        uint4 v0 = *reinterpret_cast<const uint4*>(fsrc + (size_t)c0.x * F + c);
        uint4 v1 = *reinterpret_cast<const uint4*>(fsrc + (size_t)c1.x * F + c);
        uint4 v2 = *reinterpret_cast<const uint4*>(fsrc + (size_t)c2.x * F + c);
        uint4 v3 = *reinterpret_cast<const uint4*>(fsrc + (size_t)c3.x * F + c);
        f8acc16(v0, *reinterpret_cast<__half2*>(&c0.y), hacc);
        f8acc16(v1, *reinterpret_cast<__half2*>(&c1.y), hacc);
        f8acc16(v2, *reinterpret_cast<__half2*>(&c2.y), hacc);
        f8acc16(v3, *reinterpret_cast<__half2*>(&c3.y), hacc);
    }
    for (; e < end; e++) {
        int2 ce = g_csr[e];
        uint4 v = *reinterpret_cast<const uint4*>(fsrc + (size_t)ce.x * F + c);
        f8acc16(v, *reinterpret_cast<__half2*>(&ce.y), hacc);
    }
}

// ---------------- preprocessing ---------------------------------------------
__global__ void k_zero() {
    int i = blockIdx.x * blockDim.x + threadIdx.x;
    if (i < NN) { g_deg_in[i] = 0; g_deg_out[i] = 0; }
    if (i < FMAX) g_mean[i] = 0.f;
}

__global__ void k_deg(const int* __restrict__ src, const int* __restrict__ dst) {
    int e = blockIdx.x * blockDim.x + threadIdx.x;
    if (e < EE) {
        atomicAdd(&g_deg_out[src[e]], 1);
        atomicAdd(&g_deg_in[dst[e]], 1);
    }
}

__global__ void k_scan1() {
    __shared__ int s[1024];
    int i = blockIdx.x * 1024 + threadIdx.x;
    int v = (i < NN) ? g_deg_in[i] : 0;
    s[threadIdx.x] = v;
    __syncthreads();
    for (int off = 1; off < 1024; off <<= 1) {
        int t = 0;
        if (threadIdx.x >= off) t = s[threadIdx.x - off];
        __syncthreads();
        s[threadIdx.x] += t;
        __syncthreads();
    }
    if (i < NN) g_rowptr[i] = s[threadIdx.x] - v;  // exclusive
    if (threadIdx.x == 1023) g_bsums[blockIdx.x] = s[1023];
}

__global__ void k_scan2(int nb) {
    __shared__ int s[128];
    int t = threadIdx.x;
    int v = (t < nb) ? g_bsums[t] : 0;
    s[t] = v;
    __syncthreads();
    for (int off = 1; off < 128; off <<= 1) {
        int u = 0;
        if (t >= off) u = s[t - off];
        __syncthreads();
        s[t] += u;
        __syncthreads();
    }
    if (t < nb) g_bsums[t] = s[t] - v;   // exclusive
}

__global__ void k_scan3() {
    int i = blockIdx.x * blockDim.x + threadIdx.x;
    if (i < NN) {
        int r = g_rowptr[i] + g_bsums[i >> 10];
        g_rowptr[i] = r;
        g_cursor[i] = r;
        int o = g_deg_out[i];
        g_ns[i] = (o > 0) ? rsqrtf((float)o) : 0.f;
        int d = g_deg_in[i];
        g_nd[i] = (d > 0) ? rsqrtf((float)d) : 0.f;
    }
    if (i == 0) g_rowptr[NN] = EE;
}

__global__ void k_scatter(const int* __restrict__ src, const int* __restrict__ dst,
                          const float* __restrict__ edata,
                          const float* __restrict__ mu, const float* __restrict__ sigma) {
    int e = blockIdx.x * blockDim.x + threadIdx.x;
    if (e < EE) {
        int s = src[e];
        int d = dst[e];
        float ed = edata[e];
        float m = *mu, sg = *sigma;
        float w = (ed == 1.0f) ? 1.0f : expf(-((ed - m) * (ed - m)) / sg);
        float cf = g_ns[s] * w;
        __half2 h2 = __half2half2(__float2half(cf));
        int bits;
        *reinterpret_cast<__half2*>(&bits) = h2;
        int p = atomicAdd(&g_cursor[d], 1);
        g_csr[p] = make_int2(s, bits);
    }
}

__global__ void k_copyx(const float* __restrict__ x) {
    size_t i = (size_t)blockIdx.x * blockDim.x + threadIdx.x;
    size_t stride = (size_t)gridDim.x * blockDim.x;
    for (; i < (size_t)NN * 64; i += stride)
        g_f8a[i] = (unsigned char)__nv_cvt_float_to_fp8(x[i], __NV_SATFINITE, __NV_E4M3);
}

// ---------------- weight conversion: fp32 [K,N] -> fp16 [N,K] ----------------
struct WConv {
    const float* w[11];
    int K[11];
    int N[11];
};

__global__ void k_wconv(WConv p) {
    int layer = blockIdx.y;
    int K = p.K[layer], N = p.N[layer];
    int tot = K * N;
    const float* w = p.w[layer];
    __half* out = g_w16 + (size_t)layer * WSTRIDE;
    for (int i = blockIdx.x * blockDim.x + threadIdx.x; i < tot; i += gridDim.x * blockDim.x) {
        int k = i / N, n = i % N;
        out[n * K + k] = __float2half(w[i]);
    }
}

// ---------------- HMMA helper -------------------------------------------------
__device__ __forceinline__ void mma16816(float* d, const uint32_t* a, const uint32_t* b) {
    asm volatile(
        "mma.sync.aligned.m16n8k16.row.col.f32.f16.f16.f32 "
        "{%0,%1,%2,%3}, {%4,%5,%6,%7}, {%8,%9}, {%0,%1,%2,%3};\n"
        : "+f"(d[0]), "+f"(d[1]), "+f"(d[2]), "+f"(d[3])
        : "r"(a[0]), "r"(a[1]), "r"(a[2]), "r"(a[3]), "r"(b[0]), "r"(b[1]));
}

// ---------------- FUSED spmm+gemm layer (R12 config: 256 threads) -------------
// Block = 128 nodes. Phase A: aggregate fp8 neighbors -> As smem (fp16).
// Phase B: C = leaky(As @ W + b) -> f8 out buffer (+ g_hh0 fp16 iff WH).
template<int WH>
__global__ void k_fused(const float* __restrict__ bias, int layer, int K, int Nn,
                        int lpn, int sel) {
    extern __shared__ __half sm[];
    int sak = K + 8;
    __half* As = sm;                   // 128 * sak
    __half* Bs = sm + 128 * sak;       // 64 * sak
    const unsigned char* fin = pick_c(sel);
    unsigned char* fout = pick(1 - sel);
    const __half* Wl = g_w16 + (size_t)layer * WSTRIDE;
    int tid = threadIdx.x;             // 256
    int bm = blockIdx.x * 128;

    // ---- phase A: aggregation into As ----
    for (int item = tid; item < 128 * lpn; item += 256) {
        int nl = item / lpn;
        int node = bm + nl;
        if (node < NN) {
            int c = (item - nl * lpn) * 16;
            __half2 hacc[8];
            #pragma unroll
            for (int q = 0; q < 8; q++) hacc[q] = __half2half2(__ushort_as_half(0));
            gather16(fin, K, c, g_rowptr[node], g_rowptr[node + 1], hacc);
            __half2 nd2 = __half2half2(__float2half(g_nd[node]));
            #pragma unroll
            for (int q = 0; q < 8; q++) hacc[q] = __hmul2(hacc[q], nd2);
            int4* op = reinterpret_cast<int4*>(&As[nl * sak + c]);
            op[0] = *reinterpret_cast<int4*>(&hacc[0]);
            op[1] = *reinterpret_cast<int4*>(&hacc[4]);
        }
    }
    __syncthreads();

    // ---- phase B: GEMM over N chunks of 64 ----
    int lane = tid & 31, wid = tid >> 5;
    int warpM = wid >> 1, warpN = wid & 1;
    int g = lane >> 2, tg2 = (lane & 3) * 2;
    int kq8 = K >> 3;                  // int4 loads per B row

    for (int nc = 0; nc < Nn; nc += 64) {
        for (int idx = tid; idx < 64 * kq8; idx += 256) {
            int row = idx / kq8, q = idx - row * kq8;
            int gn = nc + row;
            int4 v = make_int4(0, 0, 0, 0);
            if (gn < Nn)
                v = *reinterpret_cast<const int4*>(Wl + (size_t)gn * K + q * 8);
            *reinterpret_cast<int4*>(&Bs[row * sak + q * 8]) = v;
        }
        __syncthreads();

        float acc[2][4][4] = {};
        for (int kk = 0; kk < K; kk += 16) {
            uint32_t a[2][4], bf[4][2];
            #pragma unroll
            for (int mt = 0; mt < 2; mt++) {
                int r = warpM * 32 + mt * 16 + g;
                a[mt][0] = *reinterpret_cast<const uint32_t*>(&As[r * sak + kk + tg2]);
                a[mt][1] = *reinterpret_cast<const uint32_t*>(&As[(r + 8) * sak + kk + tg2]);
                a[mt][2] = *reinterpret_cast<const uint32_t*>(&As[r * sak + kk + tg2 + 8]);
                a[mt][3] = *reinterpret_cast<const uint32_t*>(&As[(r + 8) * sak + kk + tg2 + 8]);
            }
            #pragma unroll
            for (int nt = 0; nt < 4; nt++) {
                int n = warpN * 32 + nt * 8 + g;
                bf[nt][0] = *reinterpret_cast<const uint32_t*>(&Bs[n * sak + kk + tg2]);
                bf[nt][1] = *reinterpret_cast<const uint32_t*>(&Bs[n * sak + kk + tg2 + 8]);
            }
            #pragma unroll
            for (int mt = 0; mt < 2; mt++)
                #pragma unroll
                for (int nt = 0; nt < 4; nt++)
                    mma16816(acc[mt][nt], a[mt], bf[nt]);
        }

        // epilogue for this n-chunk
        #pragma unroll
        for (int mt = 0; mt < 2; mt++) {
            #pragma unroll
            for (int nt = 0; nt < 4; nt++) {
                int r0 = bm + warpM * 32 + mt * 16 + g;
                int c0 = nc + warpN * 32 + nt * 8 + tg2;
                float* cc = acc[mt][nt];
                #pragma unroll
                for (int hf = 0; hf < 2; hf++) {
                    int r = r0 + hf * 8;
                    if (r < NN && c0 + 1 < Nn) {
                        float v0 = cc[hf * 2 + 0] + bias[c0];
                        float v1 = cc[hf * 2 + 1] + bias[c0 + 1];
                        v0 = (v0 > 0.f) ? v0 : 0.01f * v0;
                        v1 = (v1 > 0.f) ? v1 : 0.01f * v1;
                        if (WH) {
                            *reinterpret_cast<__half2*>(g_hh0 + (size_t)r * Nn + c0) =
                                __floats2half2_rn(v0, v1);
                        }
                        *reinterpret_cast<unsigned short*>(fout + (size_t)r * Nn + c0) =
                            (unsigned short)__nv_cvt_float2_to_fp8x2(make_float2(v0, v1),
                                                                     __NV_SATFINITE, __NV_E4M3);
                    }
                }
            }
        }
        __syncthreads();
    }
}

// ---------------- standalone spmm (gemm-first layers; post-gemm) --------------
// reads z fp8 from f8[selz], writes h -> f8[1-selz] only
__global__ void k_spmm1(int F, int lpn, const float* __restrict__ bias, int selz) {
    int t = blockIdx.x * blockDim.x + threadIdx.x;
    int node = t / lpn;
    if (node >= NN) return;
    int c = (t - node * lpn) * 16;

    const unsigned char* fin = pick_c(selz);
    unsigned char* fout = pick(1 - selz);

    __half2 hacc[8];
    #pragma unroll
    for (int q = 0; q < 8; q++) hacc[q] = __half2half2(__ushort_as_half(0));
    gather16(fin, F, c, g_rowptr[node], g_rowptr[node + 1], hacc);

    float nd = g_nd[node];
    float acc[16];
    #pragma unroll
    for (int q = 0; q < 8; q++) {
        float2 f = __half22float2(hacc[q]);
        acc[2 * q + 0] = f.x * nd;
        acc[2 * q + 1] = f.y * nd;
    }
    #pragma unroll
    for (int j = 0; j < 16; j++) {
        float v = acc[j] + bias[c + j];
        acc[j] = (v > 0.f) ? v : 0.01f * v;
    }
    uint4 f8o;
    f8o.x = f8x4_pack(acc[0], acc[1], acc[2], acc[3]);
    f8o.y = f8x4_pack(acc[4], acc[5], acc[6], acc[7]);
    f8o.z = f8x4_pack(acc[8], acc[9], acc[10], acc[11]);
    f8o.w = f8x4_pack(acc[12], acc[13], acc[14], acc[15]);
    *reinterpret_cast<uint4*>(fout + (size_t)node * F + c) = f8o;
}

// ---------------- standalone gemm (gemm-first layers; pre-agg) ----------------
// z = h @ W;  A read from fp8 buffer f8[selin], output -> f8[selout]
#define SA 80
__global__ void k_gemm1(int layer, int K, int Nn, int selin, int selout) {
    const unsigned char* fin = pick_c(selin);
    unsigned char* fout = pick(selout);
    const __half* Wl = g_w16 + (size_t)layer * WSTRIDE;
    __shared__ __half As[128 * SA];
    __shared__ __half Bs[64 * SA];

    int tid = threadIdx.x;
    int lane = tid & 31, wid = tid >> 5;
    int warpM = wid >> 1, warpN = wid & 1;
    int g = lane >> 2, tg2 = (lane & 3) * 2;
    int bm = blockIdx.y * 128, bn = blockIdx.x * 64;

    float acc[2][4][4] = {};

    for (int kc = 0; kc < K; kc += 64) {
        // A tile: 128 rows x 64 k; fp8 -> fp16 conversion on load
        #pragma unroll
        for (int t = 0; t < 4; t++) {
            int idx = tid + t * 256;           // 1024 uint2 loads
            int row = idx >> 3, q = idx & 7;
            int gm = bm + row, o = kc + q * 8;
            int4 h8 = make_int4(0, 0, 0, 0);
            if (gm < NN && o < K) {
                uint2 v = *reinterpret_cast<const uint2*>(fin + (size_t)gm * K + o);
                h8 = f8x8_to_h8(v);
            }
            *reinterpret_cast<int4*>(&As[row * SA + q * 8]) = h8;
        }
        #pragma unroll
        for (int t = 0; t < 2; t++) {
            int idx = tid + t * 256;
            int row = idx >> 3, q = idx & 7;
            int gn = bn + row, o = kc + q * 8;
            int4 v = make_int4(0, 0, 0, 0);
            if (gn < Nn && o < K)
                v = *reinterpret_cast<const int4*>(Wl + (size_t)gn * K + o);
            *reinterpret_cast<int4*>(&Bs[row * SA + q * 8]) = v;
        }
        __syncthreads();

        #pragma unroll
        for (int ks = 0; ks < 4; ks++) {
            int kk = ks * 16;
            uint32_t a[2][4], bf[4][2];
            #pragma unroll
            for (int mt = 0; mt < 2; mt++) {
                int r = warpM * 32 + mt * 16 + g;
                a[mt][0] = *reinterpret_cast<const uint32_t*>(&As[r * SA + kk + tg2]);
                a[mt][1] = *reinterpret_cast<const uint32_t*>(&As[(r + 8) * SA + kk + tg2]);
                a[mt][2] = *reinterpret_cast<const uint32_t*>(&As[r * SA + kk + tg2 + 8]);
                a[mt][3] = *reinterpret_cast<const uint32_t*>(&As[(r + 8) * SA + kk + tg2 + 8]);
            }
            #pragma unroll
            for (int nt = 0; nt < 4; nt++) {
                int n = warpN * 32 + nt * 8 + g;
                bf[nt][0] = *reinterpret_cast<const uint32_t*>(&Bs[n * SA + kk + tg2]);
                bf[nt][1] = *reinterpret_cast<const uint32_t*>(&Bs[n * SA + kk + tg2 + 8]);
            }
            #pragma unroll
            for (int mt = 0; mt < 2; mt++)
                #pragma unroll
                for (int nt = 0; nt < 4; nt++)
                    mma16816(acc[mt][nt], a[mt], bf[nt]);
        }
        __syncthreads();
    }

    #pragma unroll
    for (int mt = 0; mt < 2; mt++) {
        #pragma unroll
        for (int nt = 0; nt < 4; nt++) {
            int r0 = bm + warpM * 32 + mt * 16 + g;
            int c0 = bn + warpN * 32 + nt * 8 + tg2;
            float* cc = acc[mt][nt];
            #pragma unroll
            for (int hf = 0; hf < 2; hf++) {
                int r = r0 + hf * 8;
                if (r < NN && c0 + 1 < Nn) {
                    *reinterpret_cast<unsigned short*>(fout + (size_t)r * Nn + c0) =
                        (unsigned short)__nv_cvt_float2_to_fp8x2(
                            make_float2(cc[hf * 2 + 0], cc[hf * 2 + 1]),
                            __NV_SATFINITE, __NV_E4M3);
                }
            }
        }
    }
}

// ---------------- pooling + head ---------------------------------------------
__global__ void k_mean(int F) {
    int j = threadIdx.x;      // blockDim = F (160)
    float acc = 0.f;
    for (int n = blockIdx.x; n < NN; n += gridDim.x)
        acc += __half2float(g_hh0[(size_t)n * F + j]);
    atomicAdd(&g_mean[j], acc);
}

__global__ void k_head(const float* __restrict__ Wd1, const float* __restrict__ bd1,
                       const float* __restrict__ Wd2, const float* __restrict__ bd2,
                       float* __restrict__ out) {
    __shared__ float hm[160];
    __shared__ float hd[140];
    int t = threadIdx.x;
    if (t < 160) {
        float v = g_mean[t] / (float)NN;
        hm[t] = (v > 0.f) ? v : 0.01f * v;
    }
    __syncthreads();
    if (t < 140) {
        float s = bd1[t];
        for (int k = 0; k < 160; k++) s += hm[k] * Wd1[k * 140 + t];
        hd[t] = (s > 0.f) ? s : 0.01f * s;
    }
    __syncthreads();
    if (t < 2) {
        float s = bd2[t];
        for (int k = 0; k < 140; k++) s += hd[k] * Wd2[k * 2 + t];
        out[t] = 1.0f / (1.0f + expf(-s));
    }
}

// ---------------- launch ------------------------------------------------------
extern "C" void kernel_launch(void* const* d_in, const int* in_sizes, int n_in,
                              void* d_out, int out_size) {
    const float* x     = (const float*)d_in[0];
    const int*   src   = (const int*)d_in[1];
    const int*   dst   = (const int*)d_in[2];
    const float* edata = (const float*)d_in[3];
    const float* W[11];
    const float* b[11];
    for (int i = 0; i < 11; i++) {
        W[i] = (const float*)d_in[4 + 2 * i];
        b[i] = (const float*)d_in[5 + 2 * i];
    }
    const float* Wd1 = (const float*)d_in[26];
    const float* bd1 = (const float*)d_in[27];
    const float* Wd2 = (const float*)d_in[28];
    const float* bd2 = (const float*)d_in[29];
    const float* mu    = (const float*)d_in[30];
    const float* sigma = (const float*)d_in[31];
    float* out = (float*)d_out;

    static const int dims[12] = {64, 80, 160, 112, 160, 176, 96, 144, 96, 128, 96, 160};
    static const int gfirst[11] = {0, 0, 1, 0, 0, 1, 0, 1, 0, 1, 0};

    cudaFuncSetAttribute(k_fused<0>, cudaFuncAttributeMaxDynamicSharedMemorySize, 73728);
    cudaFuncSetAttribute(k_fused<1>, cudaFuncAttributeMaxDynamicSharedMemorySize, 73728);

    k_zero<<<(NN + 255) / 256, 256>>>();
    k_deg<<<(EE + 255) / 256, 256>>>(src, dst);
    k_scan1<<<SCAN_NB, 1024>>>();
    k_scan2<<<1, 128>>>(SCAN_NB);
    k_scan3<<<(NN + 255) / 256, 256>>>();
    k_scatter<<<(EE + 255) / 256, 256>>>(src, dst, edata, mu, sigma);
    k_copyx<<<4096, 256>>>(x);

    WConv wc;
    for (int i = 0; i < 11; i++) {
        wc.w[i] = W[i];
        wc.K[i] = dims[i];
        wc.N[i] = dims[i + 1];
    }
    k_wconv<<<dim3(121, 11), 256>>>(wc);

    int cur = 0;   // which f8 buffer holds the current layer input (0=a, 1=b)
    for (int i = 0; i < 11; i++) {
        int Fi = dims[i], Fo = dims[i + 1];
        if (gfirst[i]) {
            // gemm reads h fp8 from f8[cur], writes z -> f8[1-cur];
            // spmm reads f8[1-cur], writes h -> f8[cur]
            dim3 grid((Fo + 63) / 64, (NN + 127) / 128);
            k_gemm1<<<grid, 256>>>(i, Fi, Fo, cur, 1 - cur);
            int lpn = Fo >> 4;
            int blocks = (NN * lpn + 255) / 256;
            k_spmm1<<<blocks, 256>>>(Fo, lpn, b[i], 1 - cur);
            // cur unchanged
        } else {
            int lpn = Fi >> 4;
            int smem = (128 + 64) * (Fi + 8) * 2;
            // fp16 h output needed only for the final layer (mean pool)
            if (i == 10)
                k_fused<1><<<(NN + 127) / 128, 256, smem>>>(b[i], i, Fi, Fo, lpn, cur);
            else
                k_fused<0><<<(NN + 127) / 128, 256, smem>>>(b[i], i, Fi, Fo, lpn, cur);
            cur ^= 1;
        }
    }

    k_mean<<<512, 160>>>(160);
    k_head<<<1, 160>>>(Wd1, bd1, Wd2, bd2, out);
}